// round 13
// baseline (speedup 1.0000x reference)
#include <cuda_runtime.h>
#include <cuda_fp16.h>
#include <cstdint>

// Problem constants
#define BB    8
#define CI_N  512
#define CO_N  512
#define HWN   4096
#define NCLS  35
#define SDIM  512
#define NT    8192              // total output tiles: 8 b * 32*32

// ---------------- scratch (device globals) ----------------
__device__ float g_s[BB * CI_N];
__device__ float g_cwT[CO_N * NCLS];
__device__ float g_cbT[CO_N * NCLS];
__device__ __half g_U[(size_t)16 * CO_N * CI_N];          // fragment-ordered Winograd weights
__device__ uint32_t g_V[(size_t)16 * (CI_N / 2) * NT];    // half2(ci even, ci odd)
__device__ __half g_Mh[(size_t)16 * CO_N * NT];           // GEMM results (fp16, 134MB)

// ---------------- helpers ----------------
__device__ __forceinline__ uint32_t smem_u32(const void* p) {
    uint32_t a;
    asm("{ .reg .u64 t; cvta.to.shared.u64 t, %1; cvt.u32.u64 %0, t; }" : "=r"(a) : "l"(p));
    return a;
}
__device__ __forceinline__ void cp_async16(uint32_t dst, const void* src) {
    asm volatile("cp.async.cg.shared.global [%0], [%1], 16;" :: "r"(dst), "l"(src) : "memory");
}
#define CP_COMMIT() asm volatile("cp.async.commit_group;" ::: "memory")
#define CP_WAIT(n)  asm volatile("cp.async.wait_group %0;" :: "n"(n) : "memory")

__device__ __forceinline__ void mma16(float* c, uint4 a, uint32_t b0, uint32_t b1) {
    asm volatile(
        "mma.sync.aligned.m16n8k16.row.col.f32.f16.f16.f32 "
        "{%0,%1,%2,%3}, {%4,%5,%6,%7}, {%8,%9}, {%0,%1,%2,%3};"
        : "+f"(c[0]), "+f"(c[1]), "+f"(c[2]), "+f"(c[3])
        : "r"(a.x), "r"(a.y), "r"(a.z), "r"(a.w), "r"(b0), "r"(b1));
}
__device__ __forceinline__ uint32_t pack_h2(float a, float b) {
    __half2 h = __floats2half2_rn(a, b);
    return *(uint32_t*)&h;
}

// ---------------- EqualLinear (all three jobs in one launch) ----------------
#define EQL_W0 4096
#define EQL_W1 17920
__global__ void eqlin_all_kernel(const float* __restrict__ style,
                                 const float* __restrict__ class_style,
                                 const float* __restrict__ mod_w, const float* __restrict__ mod_b,
                                 const float* __restrict__ cw_w, const float* __restrict__ cw_b,
                                 const float* __restrict__ cb_w, const float* __restrict__ cb_b)
{
    int wg = (blockIdx.x * blockDim.x + threadIdx.x) >> 5;
    int lane = threadIdx.x & 31;
    const float *X, *W, *bias;
    float* dst;
    int i, j, sj, si;
    if (wg < EQL_W0) {
        i = wg >> 9; j = wg & 511;
        X = style; W = mod_w; bias = mod_b; dst = g_s; sj = 1; si = 512;
    } else if (wg < EQL_W0 + EQL_W1) {
        int r = wg - EQL_W0;
        i = r / 512; j = r & 511;
        X = class_style; W = cw_w; bias = cw_b; dst = g_cwT; sj = NCLS; si = 1;
    } else if (wg < EQL_W0 + 2 * EQL_W1) {
        int r = wg - EQL_W0 - EQL_W1;
        i = r / 512; j = r & 511;
        X = class_style; W = cb_w; bias = cb_b; dst = g_cbT; sj = NCLS; si = 1;
    } else return;

    const float4* x4 = (const float4*)(X + (size_t)i * SDIM);
    const float4* w4 = (const float4*)(W + (size_t)j * SDIM);
    float acc = 0.f;
#pragma unroll
    for (int q = 0; q < 4; q++) {
        float4 a = x4[lane + q * 32], b = w4[lane + q * 32];
        acc += a.x * b.x + a.y * b.y + a.z * b.z + a.w * b.w;
    }
#pragma unroll
    for (int o = 16; o > 0; o >>= 1) acc += __shfl_xor_sync(0xffffffffu, acc, o);
    if (lane == 0)
        dst[j * sj + i * si] = acc * 0.04419417382415922f + bias[j];
}

// ---------------- U-prep: U = G g G^T per (co,ci), fragment-ordered fp16 ----------------
__global__ void uprep_kernel(const float* __restrict__ w)
{
    int idx = blockIdx.x * 256 + threadIdx.x;      // co*512 + ci
    if (idx >= CO_N * CI_N) return;
    int co = idx >> 9, ci = idx & 511;
    const float* gp = w + (size_t)idx * 9;
    float g0[3] = {gp[0], gp[1], gp[2]};
    float g1[3] = {gp[3], gp[4], gp[5]};
    float g2[3] = {gp[6], gp[7], gp[8]};
    float T[4][3], U[4][4];
#pragma unroll
    for (int c = 0; c < 3; c++) {
        T[0][c] = g0[c];
        T[1][c] = 0.5f * (g0[c] + g1[c] + g2[c]);
        T[2][c] = 0.5f * (g0[c] - g1[c] + g2[c]);
        T[3][c] = g2[c];
    }
#pragma unroll
    for (int r = 0; r < 4; r++) {
        U[r][0] = T[r][0];
        U[r][1] = 0.5f * (T[r][0] + T[r][1] + T[r][2]);
        U[r][2] = 0.5f * (T[r][0] - T[r][1] + T[r][2]);
        U[r][3] = T[r][2];
    }
    int cob = co >> 6;
    int c16 = ci >> 4;
    int mt = (co >> 4) & 3;
    int gg = co & 7;
    int j1 = (co >> 3) & 1;
    int t = (ci >> 1) & 3;
    int j0 = ci & 1;
    int j2 = (ci >> 3) & 1;
    int lane = (gg << 2) | t;
    int j = j0 | (j1 << 1) | (j2 << 2);
#pragma unroll
    for (int e = 0; e < 16; e++) {
        size_t addr = ((((size_t)e * 8 + cob) * 32 + c16) * 4 + mt) * 256 + lane * 8 + j;
        g_U[addr] = __float2half_rn(U[e >> 2][e & 3]);
    }
}

// ---------------- V-prep: V = B^T d B per 4x4 patch, style-scaled, half2 packed ----------------
__global__ void __launch_bounds__(256) vprep_kernel(const float* __restrict__ x)
{
    __shared__ float xs[2 * 66 * 66];
    const int tid = threadIdx.x;
    const int b = blockIdx.x >> 8;
    const int ci2 = blockIdx.x & 255;

    for (int i = tid; i < 2 * 66 * 66; i += 256) xs[i] = 0.f;
    __syncthreads();

    const float s0 = g_s[b * CI_N + 2 * ci2];
    const float s1 = g_s[b * CI_N + 2 * ci2 + 1];
    const float* x0 = x + ((size_t)b * CI_N + 2 * ci2) * HWN;
    const float* x1 = x0 + HWN;
    for (int i = tid; i < HWN; i += 256) {
        int r = i >> 6, c = i & 63;
        xs[(r + 1) * 66 + (c + 1)] = x0[i] * s0;
        xs[66 * 66 + (r + 1) * 66 + (c + 1)] = x1[i] * s1;
    }
    __syncthreads();

#pragma unroll 1
    for (int rep = 0; rep < 4; rep++) {
        int tpos = tid + rep * 256;
        int ty = tpos >> 5, tx = tpos & 31;
        float V2[2][4][4];
#pragma unroll
        for (int cin = 0; cin < 2; cin++) {
            const float* base = xs + cin * (66 * 66) + (2 * ty) * 66 + 2 * tx;
            float p[4][4];
#pragma unroll
            for (int r = 0; r < 4; r++)
#pragma unroll
                for (int c = 0; c < 4; c++) p[r][c] = base[r * 66 + c];
            float t1[4][4];
#pragma unroll
            for (int c = 0; c < 4; c++) {
                t1[0][c] = p[0][c] - p[2][c];
                t1[1][c] = p[1][c] + p[2][c];
                t1[2][c] = p[2][c] - p[1][c];
                t1[3][c] = p[1][c] - p[3][c];
            }
#pragma unroll
            for (int r = 0; r < 4; r++) {
                V2[cin][r][0] = t1[r][0] - t1[r][2];
                V2[cin][r][1] = t1[r][1] + t1[r][2];
                V2[cin][r][2] = t1[r][2] - t1[r][1];
                V2[cin][r][3] = t1[r][1] - t1[r][3];
            }
        }
        size_t n = (size_t)b * 1024 + tpos;
#pragma unroll
        for (int e = 0; e < 16; e++) {
            g_V[((size_t)e * 256 + ci2) * NT + n] =
                pack_h2(V2[0][e >> 2][e & 3], V2[1][e >> 2][e & 3]);
        }
    }
}

// ---------------- GEMM: M[e] = U[e] @ V[e]  (64co x 256n CTA tile, 4 e per CTA) ----------------
// 4-stage cp.async pipeline, k32 chunks; continuous 64-chunk mainloop over 4 e values
#define BPITCH 264   // uint32 row pitch (264 % 32 == 8 -> conflict-free frag reads)
#define ASTG   4096                       // A stage bytes: 64co x 32k fp16
#define BSTG   (16 * BPITCH * 4)          // B stage bytes (16 half2 rows) = 16896
#define NSTAGE 4
#define WG_SMEM (NSTAGE * (ASTG + BSTG))  // 83968 B

// stage global chunk q (e = e0 + q/16, cc = q%16)
__device__ __forceinline__ void gstage(uint32_t ab, uint32_t bb, int e0, int cob,
                                       int nb, int q, int tid)
{
    const int e = e0 + (q >> 4);
    const int cc = q & 15;
    const __half* asrc = g_U + (((size_t)e * 8 + cob) * 32 + 2 * cc) * 1024;
    cp_async16(ab + tid * 16, asrc + (size_t)tid * 8);
    const uint32_t* bsrc = g_V + ((size_t)e * 256 + cc * 16) * NT + nb * 256;
#pragma unroll
    for (int k = 0; k < 4; k++) {
        int idx = tid + k * 256;
        int r = idx >> 6, qq = idx & 63;
        cp_async16(bb + (r * BPITCH + qq * 4) * 4, bsrc + (size_t)r * NT + qq * 4);
    }
}

__global__ void __launch_bounds__(256, 2) wgemm_kernel()
{
    extern __shared__ __align__(16) char dsm[];

    const int tid = threadIdx.x;
    const int bx = blockIdx.x;
    // cob fastest: consecutive CTAs share the same B (V) tiles -> L2 hits
    const int cob = bx & 7, nb = (bx >> 3) & 31, e0 = (bx >> 8) * 4;
    const int wid = tid >> 5, lane = tid & 31;
    const int wco = wid & 1, wn = wid >> 1;
    const int g = lane >> 2, t = lane & 3;

    const uint32_t abase = smem_u32(dsm);
    const uint32_t bbase = abase + NSTAGE * ASTG;

    float C[2][8][4];
#pragma unroll
    for (int m = 0; m < 2; m++)
#pragma unroll
        for (int tn = 0; tn < 8; tn++)
#pragma unroll
            for (int j = 0; j < 4; j++) C[m][tn][j] = 0.f;

    // prologue: prefetch chunks 0,1,2
#pragma unroll
    for (int s = 0; s < 3; s++) {
        gstage(abase + s * ASTG, bbase + s * BSTG, e0, cob, nb, s, tid);
        CP_COMMIT();
    }

#pragma unroll 1
    for (int q = 0; q < 64; q++) {
        const int s = q & 3;
        CP_WAIT(2);
        __syncthreads();
        // prefetch chunk q+3 into slot (q+3)&3 == (q-1)&3 (freed by the sync above)
        if (q + 3 < 64)
            gstage(abase + ((q + 3) & 3) * ASTG, bbase + ((q + 3) & 3) * BSTG,
                   e0, cob, nb, q + 3, tid);
        CP_COMMIT();

        const uint4* abuf = (const uint4*)(dsm + s * ASTG);
        const uint32_t* bbuf = (const uint32_t*)(dsm + NSTAGE * ASTG + s * BSTG);
#pragma unroll
        for (int ks = 0; ks < 2; ks++) {
            uint4 A0 = abuf[ks * 128 + (2 * wco + 0) * 32 + lane];
            uint4 A1 = abuf[ks * 128 + (2 * wco + 1) * 32 + lane];
            const uint32_t* br0 = bbuf + (ks * 8 + t) * BPITCH + wn * 64 + g;
            const uint32_t* br1 = bbuf + (ks * 8 + t + 4) * BPITCH + wn * 64 + g;
#pragma unroll
            for (int tn = 0; tn < 8; tn++) {
                uint32_t b0 = br0[tn * 8];
                uint32_t b1 = br1[tn * 8];
                mma16(C[0][tn], A0, b0, b1);
                mma16(C[1][tn], A1, b0, b1);
            }
        }

        // end of an e: store M[e] and reset accumulators (overlaps next-e pipeline)
        if ((q & 15) == 15) {
            const int e = e0 + (q >> 4);
#pragma unroll
            for (int m = 0; m < 2; m++) {
                int co = cob * 64 + wco * 32 + m * 16 + g;
                __half* base = g_Mh + ((size_t)e * 512 + co) * NT + nb * 256 + wn * 64;
#pragma unroll
                for (int tn = 0; tn < 8; tn++) {
                    int col = tn * 8 + 2 * t;
                    *(uint32_t*)(base + col) = pack_h2(C[m][tn][0], C[m][tn][1]);
                    *(uint32_t*)(base + 8 * NT + col) = pack_h2(C[m][tn][2], C[m][tn][3]);
                }
            }
#pragma unroll
            for (int m = 0; m < 2; m++)
#pragma unroll
                for (int tn = 0; tn < 8; tn++)
#pragma unroll
                    for (int j = 0; j < 4; j++) C[m][tn][j] = 0.f;
        }
    }
}

// ---------------- fused: output transform + instance norm + CLADE apply ----------------
__global__ void __launch_bounds__(256) fuse_kernel(const int* __restrict__ label,
                                                   float* __restrict__ out)
{
    const int bc = blockIdx.x;            // b*512 + co
    const int b = bc >> 9, co = bc & 511;
    const int t = threadIdx.x;

    float Y[4][4];
    float s1 = 0.f, s2 = 0.f;

#pragma unroll
    for (int k = 0; k < 4; k++) {
        const size_t n = (size_t)b * 1024 + t + k * 256;
        float m[16];
#pragma unroll
        for (int e = 0; e < 16; e++)
            m[e] = __half2float(g_Mh[((size_t)e * 512 + co) * NT + n]);

        float t0[4], t1[4];
#pragma unroll
        for (int c = 0; c < 4; c++) {
            t0[c] = m[0 + c] + m[4 + c] + m[8 + c];
            t1[c] = m[4 + c] - m[8 + c] - m[12 + c];
        }
        float y00 = t0[0] + t0[1] + t0[2];
        float y01 = t0[1] - t0[2] - t0[3];
        float y10 = t1[0] + t1[1] + t1[2];
        float y11 = t1[1] - t1[2] - t1[3];
        Y[k][0] = y00; Y[k][1] = y01; Y[k][2] = y10; Y[k][3] = y11;
        s1 += (y00 + y01) + (y10 + y11);
        s2 += y00 * y00 + y01 * y01 + y10 * y10 + y11 * y11;
    }

#pragma unroll
    for (int o = 16; o > 0; o >>= 1) {
        s1 += __shfl_xor_sync(0xffffffffu, s1, o);
        s2 += __shfl_xor_sync(0xffffffffu, s2, o);
    }
    __shared__ float r1[8], r2[8];
    __shared__ float sh_mu, sh_rs;
    if ((t & 31) == 0) { r1[t >> 5] = s1; r2[t >> 5] = s2; }
    __syncthreads();
    if (t < 8) {
        s1 = r1[t]; s2 = r2[t];
#pragma unroll
        for (int o = 4; o > 0; o >>= 1) {
            s1 += __shfl_xor_sync(0xffu, s1, o);
            s2 += __shfl_xor_sync(0xffu, s2, o);
        }
        if (t == 0) {
            float mu = s1 * (1.f / 4096.f);
            float var = s2 * (1.f / 4096.f) - mu * mu;
            sh_mu = mu;
            sh_rs = rsqrtf(var + 1e-5f);
        }
    }
    __syncthreads();

    const float mu = sh_mu, rs = sh_rs;
    const float* cw = g_cwT + co * NCLS;
    const float* cb = g_cbT + co * NCLS;
    const int* lb = label + (size_t)b * HWN;
    float* ob = out + (size_t)bc * HWN;

#pragma unroll
    for (int k = 0; k < 4; k++) {
        int tpos = t + k * 256;
        int ty = tpos >> 5, tx = tpos & 31;
        int off = (2 * ty) * 64 + 2 * tx;
        int2 l0 = *(const int2*)(lb + off);
        int2 l1 = *(const int2*)(lb + off + 64);
        float2 o0, o1;
        o0.x = (Y[k][0] - mu) * rs * cw[l0.x] + cb[l0.x];
        o0.y = (Y[k][1] - mu) * rs * cw[l0.y] + cb[l0.y];
        o1.x = (Y[k][2] - mu) * rs * cw[l1.x] + cb[l1.x];
        o1.y = (Y[k][3] - mu) * rs * cw[l1.y] + cb[l1.y];
        *(float2*)(ob + off) = o0;
        *(float2*)(ob + off + 64) = o1;
    }
}

// ---------------- launch ----------------
extern "C" void kernel_launch(void* const* d_in, const int* in_sizes, int n_in,
                              void* d_out, int out_size)
{
    const float* input       = (const float*)d_in[0];
    const float* style       = (const float*)d_in[1];
    const float* class_style = (const float*)d_in[2];
    const float* weight      = (const float*)d_in[3];
    const float* mod_w       = (const float*)d_in[4];
    const float* mod_b       = (const float*)d_in[5];
    const float* cw_w        = (const float*)d_in[6];
    const float* cw_b        = (const float*)d_in[7];
    const float* cb_w        = (const float*)d_in[8];
    const float* cb_b        = (const float*)d_in[9];
    const int*   label       = (const int*)d_in[10];
    float* out = (float*)d_out;

    cudaFuncSetAttribute(wgemm_kernel,
                         cudaFuncAttributeMaxDynamicSharedMemorySize, WG_SMEM);

    int eql_blocks = (EQL_W0 + 2 * EQL_W1 + 7) / 8;
    eqlin_all_kernel<<<eql_blocks, 256>>>(style, class_style, mod_w, mod_b,
                                          cw_w, cw_b, cb_w, cb_b);

    uprep_kernel<<<(CO_N * CI_N + 255) / 256, 256>>>(weight);
    vprep_kernel<<<BB * 256, 256>>>(input);

    wgemm_kernel<<<8 * 32 * 4, 256, WG_SMEM>>>();

    fuse_kernel<<<BB * CO_N, 256>>>(label, out);
}

// round 14
// speedup vs baseline: 1.0044x; 1.0044x over previous
#include <cuda_runtime.h>
#include <cuda_fp16.h>
#include <cstdint>

// Problem constants
#define BB    8
#define CI_N  512
#define CO_N  512
#define HWN   4096
#define NCLS  35
#define SDIM  512
#define NT    8192              // total output tiles: 8 b * 32*32

// ---------------- scratch (device globals) ----------------
__device__ float g_s[BB * CI_N];
__device__ float g_cwT[CO_N * NCLS];
__device__ float g_cbT[CO_N * NCLS];
__device__ __half g_U[(size_t)16 * CO_N * CI_N];          // fragment-ordered Winograd weights
__device__ uint32_t g_V[(size_t)16 * (CI_N / 2) * NT];    // half2(ci even, ci odd)
__device__ __half g_Mh[(size_t)16 * CO_N * NT];           // GEMM results (fp16, 134MB)

// ---------------- helpers ----------------
__device__ __forceinline__ uint32_t smem_u32(const void* p) {
    uint32_t a;
    asm("{ .reg .u64 t; cvta.to.shared.u64 t, %1; cvt.u32.u64 %0, t; }" : "=r"(a) : "l"(p));
    return a;
}
__device__ __forceinline__ void cp_async16(uint32_t dst, const void* src) {
    asm volatile("cp.async.cg.shared.global [%0], [%1], 16;" :: "r"(dst), "l"(src) : "memory");
}
#define CP_COMMIT() asm volatile("cp.async.commit_group;" ::: "memory")
#define CP_WAIT(n)  asm volatile("cp.async.wait_group %0;" :: "n"(n) : "memory")

__device__ __forceinline__ void mma16(float* c, uint4 a, uint32_t b0, uint32_t b1) {
    asm volatile(
        "mma.sync.aligned.m16n8k16.row.col.f32.f16.f16.f32 "
        "{%0,%1,%2,%3}, {%4,%5,%6,%7}, {%8,%9}, {%0,%1,%2,%3};"
        : "+f"(c[0]), "+f"(c[1]), "+f"(c[2]), "+f"(c[3])
        : "r"(a.x), "r"(a.y), "r"(a.z), "r"(a.w), "r"(b0), "r"(b1));
}
__device__ __forceinline__ uint32_t pack_h2(float a, float b) {
    __half2 h = __floats2half2_rn(a, b);
    return *(uint32_t*)&h;
}

// ---------------- EqualLinear (all three jobs in one launch) ----------------
#define EQL_W0 4096
#define EQL_W1 17920
__global__ void eqlin_all_kernel(const float* __restrict__ style,
                                 const float* __restrict__ class_style,
                                 const float* __restrict__ mod_w, const float* __restrict__ mod_b,
                                 const float* __restrict__ cw_w, const float* __restrict__ cw_b,
                                 const float* __restrict__ cb_w, const float* __restrict__ cb_b)
{
    int wg = (blockIdx.x * blockDim.x + threadIdx.x) >> 5;
    int lane = threadIdx.x & 31;
    const float *X, *W, *bias;
    float* dst;
    int i, j, sj, si;
    if (wg < EQL_W0) {
        i = wg >> 9; j = wg & 511;
        X = style; W = mod_w; bias = mod_b; dst = g_s; sj = 1; si = 512;
    } else if (wg < EQL_W0 + EQL_W1) {
        int r = wg - EQL_W0;
        i = r / 512; j = r & 511;
        X = class_style; W = cw_w; bias = cw_b; dst = g_cwT; sj = NCLS; si = 1;
    } else if (wg < EQL_W0 + 2 * EQL_W1) {
        int r = wg - EQL_W0 - EQL_W1;
        i = r / 512; j = r & 511;
        X = class_style; W = cb_w; bias = cb_b; dst = g_cbT; sj = NCLS; si = 1;
    } else return;

    const float4* x4 = (const float4*)(X + (size_t)i * SDIM);
    const float4* w4 = (const float4*)(W + (size_t)j * SDIM);
    float acc = 0.f;
#pragma unroll
    for (int q = 0; q < 4; q++) {
        float4 a = x4[lane + q * 32], b = w4[lane + q * 32];
        acc += a.x * b.x + a.y * b.y + a.z * b.z + a.w * b.w;
    }
#pragma unroll
    for (int o = 16; o > 0; o >>= 1) acc += __shfl_xor_sync(0xffffffffu, acc, o);
    if (lane == 0)
        dst[j * sj + i * si] = acc * 0.04419417382415922f + bias[j];
}

// ---------------- U-prep: U = G g G^T per (co,ci), fragment-ordered fp16 ----------------
__global__ void uprep_kernel(const float* __restrict__ w)
{
    int idx = blockIdx.x * 256 + threadIdx.x;      // co*512 + ci
    if (idx >= CO_N * CI_N) return;
    int co = idx >> 9, ci = idx & 511;
    const float* gp = w + (size_t)idx * 9;
    float g0[3] = {gp[0], gp[1], gp[2]};
    float g1[3] = {gp[3], gp[4], gp[5]};
    float g2[3] = {gp[6], gp[7], gp[8]};
    float T[4][3], U[4][4];
#pragma unroll
    for (int c = 0; c < 3; c++) {
        T[0][c] = g0[c];
        T[1][c] = 0.5f * (g0[c] + g1[c] + g2[c]);
        T[2][c] = 0.5f * (g0[c] - g1[c] + g2[c]);
        T[3][c] = g2[c];
    }
#pragma unroll
    for (int r = 0; r < 4; r++) {
        U[r][0] = T[r][0];
        U[r][1] = 0.5f * (T[r][0] + T[r][1] + T[r][2]);
        U[r][2] = 0.5f * (T[r][0] - T[r][1] + T[r][2]);
        U[r][3] = T[r][2];
    }
    int cob = co >> 6;
    int c16 = ci >> 4;
    int mt = (co >> 4) & 3;
    int gg = co & 7;
    int j1 = (co >> 3) & 1;
    int t = (ci >> 1) & 3;
    int j0 = ci & 1;
    int j2 = (ci >> 3) & 1;
    int lane = (gg << 2) | t;
    int j = j0 | (j1 << 1) | (j2 << 2);
#pragma unroll
    for (int e = 0; e < 16; e++) {
        size_t addr = ((((size_t)e * 8 + cob) * 32 + c16) * 4 + mt) * 256 + lane * 8 + j;
        g_U[addr] = __float2half_rn(U[e >> 2][e & 3]);
    }
}

// ---------------- V-prep: V = B^T d B per 4x4 patch, style-scaled, half2 packed ----------------
__global__ void __launch_bounds__(256) vprep_kernel(const float* __restrict__ x)
{
    __shared__ float xs[2 * 66 * 66];
    const int tid = threadIdx.x;
    const int b = blockIdx.x >> 8;
    const int ci2 = blockIdx.x & 255;

    for (int i = tid; i < 2 * 66 * 66; i += 256) xs[i] = 0.f;
    __syncthreads();

    const float s0 = g_s[b * CI_N + 2 * ci2];
    const float s1 = g_s[b * CI_N + 2 * ci2 + 1];
    const float* x0 = x + ((size_t)b * CI_N + 2 * ci2) * HWN;
    const float* x1 = x0 + HWN;
    for (int i = tid; i < HWN; i += 256) {
        int r = i >> 6, c = i & 63;
        xs[(r + 1) * 66 + (c + 1)] = x0[i] * s0;
        xs[66 * 66 + (r + 1) * 66 + (c + 1)] = x1[i] * s1;
    }
    __syncthreads();

#pragma unroll 1
    for (int rep = 0; rep < 4; rep++) {
        int tpos = tid + rep * 256;
        int ty = tpos >> 5, tx = tpos & 31;
        float V2[2][4][4];
#pragma unroll
        for (int cin = 0; cin < 2; cin++) {
            const float* base = xs + cin * (66 * 66) + (2 * ty) * 66 + 2 * tx;
            float p[4][4];
#pragma unroll
            for (int r = 0; r < 4; r++)
#pragma unroll
                for (int c = 0; c < 4; c++) p[r][c] = base[r * 66 + c];
            float t1[4][4];
#pragma unroll
            for (int c = 0; c < 4; c++) {
                t1[0][c] = p[0][c] - p[2][c];
                t1[1][c] = p[1][c] + p[2][c];
                t1[2][c] = p[2][c] - p[1][c];
                t1[3][c] = p[1][c] - p[3][c];
            }
#pragma unroll
            for (int r = 0; r < 4; r++) {
                V2[cin][r][0] = t1[r][0] - t1[r][2];
                V2[cin][r][1] = t1[r][1] + t1[r][2];
                V2[cin][r][2] = t1[r][2] - t1[r][1];
                V2[cin][r][3] = t1[r][1] - t1[r][3];
            }
        }
        size_t n = (size_t)b * 1024 + tpos;
#pragma unroll
        for (int e = 0; e < 16; e++) {
            g_V[((size_t)e * 256 + ci2) * NT + n] =
                pack_h2(V2[0][e >> 2][e & 3], V2[1][e >> 2][e & 3]);
        }
    }
}

// ---------------- GEMM: M[e] = U[e] @ V[e]  (64co x 256n CTA tile, 4 e per CTA) ----------------
// 4-stage cp.async pipeline, k32 chunks; continuous 64-chunk mainloop over 4 e values
#define BPITCH 264   // uint32 row pitch (264 % 32 == 8 -> conflict-free frag reads)
#define ASTG   4096                       // A stage bytes: 64co x 32k fp16
#define BSTG   (16 * BPITCH * 4)          // B stage bytes (16 half2 rows) = 16896
#define NSTAGE 4
#define WG_SMEM (NSTAGE * (ASTG + BSTG))  // 83968 B

// stage global chunk q (e = e0 + q/16, cc = q%16)
__device__ __forceinline__ void gstage(uint32_t ab, uint32_t bb, int e0, int cob,
                                       int nb, int q, int tid)
{
    const int e = e0 + (q >> 4);
    const int cc = q & 15;
    const __half* asrc = g_U + (((size_t)e * 8 + cob) * 32 + 2 * cc) * 1024;
    cp_async16(ab + tid * 16, asrc + (size_t)tid * 8);
    const uint32_t* bsrc = g_V + ((size_t)e * 256 + cc * 16) * NT + nb * 256;
#pragma unroll
    for (int k = 0; k < 4; k++) {
        int idx = tid + k * 256;
        int r = idx >> 6, qq = idx & 63;
        cp_async16(bb + (r * BPITCH + qq * 4) * 4, bsrc + (size_t)r * NT + qq * 4);
    }
}

__global__ void __launch_bounds__(256, 2) wgemm_kernel()
{
    extern __shared__ __align__(16) char dsm[];

    const int tid = threadIdx.x;
    const int bx = blockIdx.x;
    // cob fastest: consecutive CTAs share the same B (V) tiles -> L2 hits
    const int cob = bx & 7, nb = (bx >> 3) & 31, e0 = (bx >> 8) * 4;
    const int wid = tid >> 5, lane = tid & 31;
    const int wco = wid & 1, wn = wid >> 1;
    const int g = lane >> 2, t = lane & 3;

    const uint32_t abase = smem_u32(dsm);
    const uint32_t bbase = abase + NSTAGE * ASTG;

    float C[2][8][4];
#pragma unroll
    for (int m = 0; m < 2; m++)
#pragma unroll
        for (int tn = 0; tn < 8; tn++)
#pragma unroll
            for (int j = 0; j < 4; j++) C[m][tn][j] = 0.f;

    // prologue: prefetch chunks 0,1,2
#pragma unroll
    for (int s = 0; s < 3; s++) {
        gstage(abase + s * ASTG, bbase + s * BSTG, e0, cob, nb, s, tid);
        CP_COMMIT();
    }

#pragma unroll 1
    for (int q = 0; q < 64; q++) {
        const int s = q & 3;
        CP_WAIT(2);
        __syncthreads();
        // prefetch chunk q+3 into slot (q+3)&3 == (q-1)&3 (freed by the sync above)
        if (q + 3 < 64)
            gstage(abase + ((q + 3) & 3) * ASTG, bbase + ((q + 3) & 3) * BSTG,
                   e0, cob, nb, q + 3, tid);
        CP_COMMIT();

        const uint4* abuf = (const uint4*)(dsm + s * ASTG);
        const uint32_t* bbuf = (const uint32_t*)(dsm + NSTAGE * ASTG + s * BSTG);
#pragma unroll
        for (int ks = 0; ks < 2; ks++) {
            uint4 A0 = abuf[ks * 128 + (2 * wco + 0) * 32 + lane];
            uint4 A1 = abuf[ks * 128 + (2 * wco + 1) * 32 + lane];
            const uint32_t* br0 = bbuf + (ks * 8 + t) * BPITCH + wn * 64 + g;
            const uint32_t* br1 = bbuf + (ks * 8 + t + 4) * BPITCH + wn * 64 + g;
#pragma unroll
            for (int tn = 0; tn < 8; tn++) {
                uint32_t b0 = br0[tn * 8];
                uint32_t b1 = br1[tn * 8];
                mma16(C[0][tn], A0, b0, b1);
                mma16(C[1][tn], A1, b0, b1);
            }
        }

        // end of an e: store M[e] and reset accumulators (overlaps next-e pipeline)
        if ((q & 15) == 15) {
            const int e = e0 + (q >> 4);
#pragma unroll
            for (int m = 0; m < 2; m++) {
                int co = cob * 64 + wco * 32 + m * 16 + g;
                __half* base = g_Mh + ((size_t)e * 512 + co) * NT + nb * 256 + wn * 64;
#pragma unroll
                for (int tn = 0; tn < 8; tn++) {
                    int col = tn * 8 + 2 * t;
                    *(uint32_t*)(base + col) = pack_h2(C[m][tn][0], C[m][tn][1]);
                    *(uint32_t*)(base + 8 * NT + col) = pack_h2(C[m][tn][2], C[m][tn][3]);
                }
            }
#pragma unroll
            for (int m = 0; m < 2; m++)
#pragma unroll
                for (int tn = 0; tn < 8; tn++)
#pragma unroll
                    for (int j = 0; j < 4; j++) C[m][tn][j] = 0.f;
        }
    }
}

// ---------------- fused: output transform + instance norm + CLADE apply ----------------
__global__ void __launch_bounds__(256) fuse_kernel(const int* __restrict__ label,
                                                   float* __restrict__ out)
{
    const int bc = blockIdx.x;            // b*512 + co
    const int b = bc >> 9, co = bc & 511;
    const int t = threadIdx.x;

    float Y[4][4];
    float s1 = 0.f, s2 = 0.f;

#pragma unroll
    for (int k = 0; k < 4; k++) {
        const size_t n = (size_t)b * 1024 + t + k * 256;
        float m[16];
#pragma unroll
        for (int e = 0; e < 16; e++)
            m[e] = __half2float(g_Mh[((size_t)e * 512 + co) * NT + n]);

        float t0[4], t1[4];
#pragma unroll
        for (int c = 0; c < 4; c++) {
            t0[c] = m[0 + c] + m[4 + c] + m[8 + c];
            t1[c] = m[4 + c] - m[8 + c] - m[12 + c];
        }
        float y00 = t0[0] + t0[1] + t0[2];
        float y01 = t0[1] - t0[2] - t0[3];
        float y10 = t1[0] + t1[1] + t1[2];
        float y11 = t1[1] - t1[2] - t1[3];
        Y[k][0] = y00; Y[k][1] = y01; Y[k][2] = y10; Y[k][3] = y11;
        s1 += (y00 + y01) + (y10 + y11);
        s2 += y00 * y00 + y01 * y01 + y10 * y10 + y11 * y11;
    }

#pragma unroll
    for (int o = 16; o > 0; o >>= 1) {
        s1 += __shfl_xor_sync(0xffffffffu, s1, o);
        s2 += __shfl_xor_sync(0xffffffffu, s2, o);
    }
    __shared__ float r1[8], r2[8];
    __shared__ float sh_mu, sh_rs;
    if ((t & 31) == 0) { r1[t >> 5] = s1; r2[t >> 5] = s2; }
    __syncthreads();
    if (t < 8) {
        s1 = r1[t]; s2 = r2[t];
#pragma unroll
        for (int o = 4; o > 0; o >>= 1) {
            s1 += __shfl_xor_sync(0xffu, s1, o);
            s2 += __shfl_xor_sync(0xffu, s2, o);
        }
        if (t == 0) {
            float mu = s1 * (1.f / 4096.f);
            float var = s2 * (1.f / 4096.f) - mu * mu;
            sh_mu = mu;
            sh_rs = rsqrtf(var + 1e-5f);
        }
    }
    __syncthreads();

    const float mu = sh_mu, rs = sh_rs;
    const float* cw = g_cwT + co * NCLS;
    const float* cb = g_cbT + co * NCLS;
    const int* lb = label + (size_t)b * HWN;
    float* ob = out + (size_t)bc * HWN;

#pragma unroll
    for (int k = 0; k < 4; k++) {
        int tpos = t + k * 256;
        int ty = tpos >> 5, tx = tpos & 31;
        int off = (2 * ty) * 64 + 2 * tx;
        int2 l0 = *(const int2*)(lb + off);
        int2 l1 = *(const int2*)(lb + off + 64);
        float2 o0, o1;
        o0.x = (Y[k][0] - mu) * rs * cw[l0.x] + cb[l0.x];
        o0.y = (Y[k][1] - mu) * rs * cw[l0.y] + cb[l0.y];
        o1.x = (Y[k][2] - mu) * rs * cw[l1.x] + cb[l1.x];
        o1.y = (Y[k][3] - mu) * rs * cw[l1.y] + cb[l1.y];
        *(float2*)(ob + off) = o0;
        *(float2*)(ob + off + 64) = o1;
    }
}

// ---------------- launch ----------------
extern "C" void kernel_launch(void* const* d_in, const int* in_sizes, int n_in,
                              void* d_out, int out_size)
{
    const float* input       = (const float*)d_in[0];
    const float* style       = (const float*)d_in[1];
    const float* class_style = (const float*)d_in[2];
    const float* weight      = (const float*)d_in[3];
    const float* mod_w       = (const float*)d_in[4];
    const float* mod_b       = (const float*)d_in[5];
    const float* cw_w        = (const float*)d_in[6];
    const float* cw_b        = (const float*)d_in[7];
    const float* cb_w        = (const float*)d_in[8];
    const float* cb_b        = (const float*)d_in[9];
    const int*   label       = (const int*)d_in[10];
    float* out = (float*)d_out;

    cudaFuncSetAttribute(wgemm_kernel,
                         cudaFuncAttributeMaxDynamicSharedMemorySize, WG_SMEM);

    int eql_blocks = (EQL_W0 + 2 * EQL_W1 + 7) / 8;
    eqlin_all_kernel<<<eql_blocks, 256>>>(style, class_style, mod_w, mod_b,
                                          cw_w, cw_b, cb_w, cb_b);

    uprep_kernel<<<(CO_N * CI_N + 255) / 256, 256>>>(weight);
    vprep_kernel<<<BB * 256, 256>>>(input);

    wgemm_kernel<<<8 * 32 * 4, 256, WG_SMEM>>>();

    fuse_kernel<<<BB * CO_N, 256>>>(label, out);
}

// round 15
// speedup vs baseline: 1.0064x; 1.0021x over previous
#include <cuda_runtime.h>
#include <cuda_fp16.h>
#include <cstdint>

// Problem constants
#define BB    8
#define CI_N  512
#define CO_N  512
#define HWN   4096
#define NCLS  35
#define SDIM  512
#define NT    8192              // total output tiles: 8 b * 32*32

// ---------------- scratch (device globals) ----------------
__device__ float g_s[BB * CI_N];
__device__ float g_cwT[CO_N * NCLS];
__device__ float g_cbT[CO_N * NCLS];
__device__ __half g_U[(size_t)16 * CO_N * CI_N];          // fragment-ordered Winograd weights
__device__ uint32_t g_V[(size_t)16 * (CI_N / 2) * NT];    // half2(ci even, ci odd)
__device__ __half g_Mh[(size_t)16 * CO_N * NT];           // GEMM results (fp16, 134MB)

// ---------------- helpers ----------------
__device__ __forceinline__ uint32_t smem_u32(const void* p) {
    uint32_t a;
    asm("{ .reg .u64 t; cvta.to.shared.u64 t, %1; cvt.u32.u64 %0, t; }" : "=r"(a) : "l"(p));
    return a;
}
__device__ __forceinline__ void cp_async16(uint32_t dst, const void* src) {
    asm volatile("cp.async.cg.shared.global [%0], [%1], 16;" :: "r"(dst), "l"(src) : "memory");
}
#define CP_COMMIT() asm volatile("cp.async.commit_group;" ::: "memory")
#define CP_WAIT(n)  asm volatile("cp.async.wait_group %0;" :: "n"(n) : "memory")

__device__ __forceinline__ void mma16(float* c, uint4 a, uint32_t b0, uint32_t b1) {
    asm volatile(
        "mma.sync.aligned.m16n8k16.row.col.f32.f16.f16.f32 "
        "{%0,%1,%2,%3}, {%4,%5,%6,%7}, {%8,%9}, {%0,%1,%2,%3};"
        : "+f"(c[0]), "+f"(c[1]), "+f"(c[2]), "+f"(c[3])
        : "r"(a.x), "r"(a.y), "r"(a.z), "r"(a.w), "r"(b0), "r"(b1));
}
__device__ __forceinline__ uint32_t pack_h2(float a, float b) {
    __half2 h = __floats2half2_rn(a, b);
    return *(uint32_t*)&h;
}

// ---------------- EqualLinear (all three jobs in one launch) ----------------
#define EQL_W0 4096
#define EQL_W1 17920
__global__ void eqlin_all_kernel(const float* __restrict__ style,
                                 const float* __restrict__ class_style,
                                 const float* __restrict__ mod_w, const float* __restrict__ mod_b,
                                 const float* __restrict__ cw_w, const float* __restrict__ cw_b,
                                 const float* __restrict__ cb_w, const float* __restrict__ cb_b)
{
    int wg = (blockIdx.x * blockDim.x + threadIdx.x) >> 5;
    int lane = threadIdx.x & 31;
    const float *X, *W, *bias;
    float* dst;
    int i, j, sj, si;
    if (wg < EQL_W0) {
        i = wg >> 9; j = wg & 511;
        X = style; W = mod_w; bias = mod_b; dst = g_s; sj = 1; si = 512;
    } else if (wg < EQL_W0 + EQL_W1) {
        int r = wg - EQL_W0;
        i = r / 512; j = r & 511;
        X = class_style; W = cw_w; bias = cw_b; dst = g_cwT; sj = NCLS; si = 1;
    } else if (wg < EQL_W0 + 2 * EQL_W1) {
        int r = wg - EQL_W0 - EQL_W1;
        i = r / 512; j = r & 511;
        X = class_style; W = cb_w; bias = cb_b; dst = g_cbT; sj = NCLS; si = 1;
    } else return;

    const float4* x4 = (const float4*)(X + (size_t)i * SDIM);
    const float4* w4 = (const float4*)(W + (size_t)j * SDIM);
    float acc = 0.f;
#pragma unroll
    for (int q = 0; q < 4; q++) {
        float4 a = x4[lane + q * 32], b = w4[lane + q * 32];
        acc += a.x * b.x + a.y * b.y + a.z * b.z + a.w * b.w;
    }
#pragma unroll
    for (int o = 16; o > 0; o >>= 1) acc += __shfl_xor_sync(0xffffffffu, acc, o);
    if (lane == 0)
        dst[j * sj + i * si] = acc * 0.04419417382415922f + bias[j];
}

// ---------------- U-prep: U = G g G^T per (co,ci), fragment-ordered fp16 ----------------
__global__ void uprep_kernel(const float* __restrict__ w)
{
    int idx = blockIdx.x * 256 + threadIdx.x;      // co*512 + ci
    if (idx >= CO_N * CI_N) return;
    int co = idx >> 9, ci = idx & 511;
    const float* gp = w + (size_t)idx * 9;
    float g0[3] = {gp[0], gp[1], gp[2]};
    float g1[3] = {gp[3], gp[4], gp[5]};
    float g2[3] = {gp[6], gp[7], gp[8]};
    float T[4][3], U[4][4];
#pragma unroll
    for (int c = 0; c < 3; c++) {
        T[0][c] = g0[c];
        T[1][c] = 0.5f * (g0[c] + g1[c] + g2[c]);
        T[2][c] = 0.5f * (g0[c] - g1[c] + g2[c]);
        T[3][c] = g2[c];
    }
#pragma unroll
    for (int r = 0; r < 4; r++) {
        U[r][0] = T[r][0];
        U[r][1] = 0.5f * (T[r][0] + T[r][1] + T[r][2]);
        U[r][2] = 0.5f * (T[r][0] - T[r][1] + T[r][2]);
        U[r][3] = T[r][2];
    }
    int cob = co >> 6;
    int c16 = ci >> 4;
    int mt = (co >> 4) & 3;
    int gg = co & 7;
    int j1 = (co >> 3) & 1;
    int t = (ci >> 1) & 3;
    int j0 = ci & 1;
    int j2 = (ci >> 3) & 1;
    int lane = (gg << 2) | t;
    int j = j0 | (j1 << 1) | (j2 << 2);
#pragma unroll
    for (int e = 0; e < 16; e++) {
        size_t addr = ((((size_t)e * 8 + cob) * 32 + c16) * 4 + mt) * 256 + lane * 8 + j;
        g_U[addr] = __float2half_rn(U[e >> 2][e & 3]);
    }
}

// ---------------- V-prep: V = B^T d B per 4x4 patch, style-scaled, half2 packed ----------------
__global__ void __launch_bounds__(256) vprep_kernel(const float* __restrict__ x)
{
    __shared__ float xs[2 * 66 * 66];
    const int tid = threadIdx.x;
    const int b = blockIdx.x >> 8;
    const int ci2 = blockIdx.x & 255;

    for (int i = tid; i < 2 * 66 * 66; i += 256) xs[i] = 0.f;
    __syncthreads();

    const float s0 = g_s[b * CI_N + 2 * ci2];
    const float s1 = g_s[b * CI_N + 2 * ci2 + 1];
    const float* x0 = x + ((size_t)b * CI_N + 2 * ci2) * HWN;
    const float* x1 = x0 + HWN;
    for (int i = tid; i < HWN; i += 256) {
        int r = i >> 6, c = i & 63;
        xs[(r + 1) * 66 + (c + 1)] = x0[i] * s0;
        xs[66 * 66 + (r + 1) * 66 + (c + 1)] = x1[i] * s1;
    }
    __syncthreads();

#pragma unroll 1
    for (int rep = 0; rep < 4; rep++) {
        int tpos = tid + rep * 256;
        int ty = tpos >> 5, tx = tpos & 31;
        float V2[2][4][4];
#pragma unroll
        for (int cin = 0; cin < 2; cin++) {
            const float* base = xs + cin * (66 * 66) + (2 * ty) * 66 + 2 * tx;
            float p[4][4];
#pragma unroll
            for (int r = 0; r < 4; r++)
#pragma unroll
                for (int c = 0; c < 4; c++) p[r][c] = base[r * 66 + c];
            float t1[4][4];
#pragma unroll
            for (int c = 0; c < 4; c++) {
                t1[0][c] = p[0][c] - p[2][c];
                t1[1][c] = p[1][c] + p[2][c];
                t1[2][c] = p[2][c] - p[1][c];
                t1[3][c] = p[1][c] - p[3][c];
            }
#pragma unroll
            for (int r = 0; r < 4; r++) {
                V2[cin][r][0] = t1[r][0] - t1[r][2];
                V2[cin][r][1] = t1[r][1] + t1[r][2];
                V2[cin][r][2] = t1[r][2] - t1[r][1];
                V2[cin][r][3] = t1[r][1] - t1[r][3];
            }
        }
        size_t n = (size_t)b * 1024 + tpos;
#pragma unroll
        for (int e = 0; e < 16; e++) {
            g_V[((size_t)e * 256 + ci2) * NT + n] =
                pack_h2(V2[0][e >> 2][e & 3], V2[1][e >> 2][e & 3]);
        }
    }
}

// ---------------- GEMM: M[e] = U[e] @ V[e]  (64co x 256n CTA tile, 4 e per CTA) ----------------
// 4-stage cp.async pipeline, k32 chunks; continuous 64-chunk mainloop over 4 e values
#define BPITCH 264   // uint32 row pitch (264 % 32 == 8 -> conflict-free frag reads)
#define ASTG   4096                       // A stage bytes: 64co x 32k fp16
#define BSTG   (16 * BPITCH * 4)          // B stage bytes (16 half2 rows) = 16896
#define NSTAGE 4
#define WG_SMEM (NSTAGE * (ASTG + BSTG))  // 83968 B

// stage global chunk q (e = e0 + q/16, cc = q%16)
__device__ __forceinline__ void gstage(uint32_t ab, uint32_t bb, int e0, int cob,
                                       int nb, int q, int tid)
{
    const int e = e0 + (q >> 4);
    const int cc = q & 15;
    const __half* asrc = g_U + (((size_t)e * 8 + cob) * 32 + 2 * cc) * 1024;
    cp_async16(ab + tid * 16, asrc + (size_t)tid * 8);
    const uint32_t* bsrc = g_V + ((size_t)e * 256 + cc * 16) * NT + nb * 256;
#pragma unroll
    for (int k = 0; k < 4; k++) {
        int idx = tid + k * 256;
        int r = idx >> 6, qq = idx & 63;
        cp_async16(bb + (r * BPITCH + qq * 4) * 4, bsrc + (size_t)r * NT + qq * 4);
    }
}

__global__ void __launch_bounds__(256, 2) wgemm_kernel()
{
    extern __shared__ __align__(16) char dsm[];

    const int tid = threadIdx.x;
    const int bx = blockIdx.x;
    // cob fastest: consecutive CTAs share the same B (V) tiles -> L2 hits
    const int cob = bx & 7, nb = (bx >> 3) & 31, e0 = (bx >> 8) * 4;
    const int wid = tid >> 5, lane = tid & 31;
    const int wco = wid & 1, wn = wid >> 1;
    const int g = lane >> 2, t = lane & 3;

    const uint32_t abase = smem_u32(dsm);
    const uint32_t bbase = abase + NSTAGE * ASTG;

    float C[2][8][4];
#pragma unroll
    for (int m = 0; m < 2; m++)
#pragma unroll
        for (int tn = 0; tn < 8; tn++)
#pragma unroll
            for (int j = 0; j < 4; j++) C[m][tn][j] = 0.f;

    // prologue: prefetch chunks 0,1,2
#pragma unroll
    for (int s = 0; s < 3; s++) {
        gstage(abase + s * ASTG, bbase + s * BSTG, e0, cob, nb, s, tid);
        CP_COMMIT();
    }

#pragma unroll 1
    for (int q = 0; q < 64; q++) {
        const int s = q & 3;
        CP_WAIT(2);
        __syncthreads();
        // prefetch chunk q+3 into slot (q+3)&3 == (q-1)&3 (freed by the sync above)
        if (q + 3 < 64)
            gstage(abase + ((q + 3) & 3) * ASTG, bbase + ((q + 3) & 3) * BSTG,
                   e0, cob, nb, q + 3, tid);
        CP_COMMIT();

        const uint4* abuf = (const uint4*)(dsm + s * ASTG);
        const uint32_t* bbuf = (const uint32_t*)(dsm + NSTAGE * ASTG + s * BSTG);
#pragma unroll
        for (int ks = 0; ks < 2; ks++) {
            uint4 A0 = abuf[ks * 128 + (2 * wco + 0) * 32 + lane];
            uint4 A1 = abuf[ks * 128 + (2 * wco + 1) * 32 + lane];
            const uint32_t* br0 = bbuf + (ks * 8 + t) * BPITCH + wn * 64 + g;
            const uint32_t* br1 = bbuf + (ks * 8 + t + 4) * BPITCH + wn * 64 + g;
#pragma unroll
            for (int tn = 0; tn < 8; tn++) {
                uint32_t b0 = br0[tn * 8];
                uint32_t b1 = br1[tn * 8];
                mma16(C[0][tn], A0, b0, b1);
                mma16(C[1][tn], A1, b0, b1);
            }
        }

        // end of an e: store M[e] and reset accumulators (overlaps next-e pipeline)
        if ((q & 15) == 15) {
            const int e = e0 + (q >> 4);
#pragma unroll
            for (int m = 0; m < 2; m++) {
                int co = cob * 64 + wco * 32 + m * 16 + g;
                __half* base = g_Mh + ((size_t)e * 512 + co) * NT + nb * 256 + wn * 64;
#pragma unroll
                for (int tn = 0; tn < 8; tn++) {
                    int col = tn * 8 + 2 * t;
                    *(uint32_t*)(base + col) = pack_h2(C[m][tn][0], C[m][tn][1]);
                    *(uint32_t*)(base + 8 * NT + col) = pack_h2(C[m][tn][2], C[m][tn][3]);
                }
            }
#pragma unroll
            for (int m = 0; m < 2; m++)
#pragma unroll
                for (int tn = 0; tn < 8; tn++)
#pragma unroll
                    for (int j = 0; j < 4; j++) C[m][tn][j] = 0.f;
        }
    }
}

// ---------------- fused: output transform + instance norm + CLADE apply ----------------
__global__ void __launch_bounds__(256) fuse_kernel(const int* __restrict__ label,
                                                   float* __restrict__ out)
{
    const int bc = blockIdx.x;            // b*512 + co
    const int b = bc >> 9, co = bc & 511;
    const int t = threadIdx.x;

    float Y[4][4];
    float s1 = 0.f, s2 = 0.f;

#pragma unroll
    for (int k = 0; k < 4; k++) {
        const size_t n = (size_t)b * 1024 + t + k * 256;
        float m[16];
#pragma unroll
        for (int e = 0; e < 16; e++)
            m[e] = __half2float(g_Mh[((size_t)e * 512 + co) * NT + n]);

        float t0[4], t1[4];
#pragma unroll
        for (int c = 0; c < 4; c++) {
            t0[c] = m[0 + c] + m[4 + c] + m[8 + c];
            t1[c] = m[4 + c] - m[8 + c] - m[12 + c];
        }
        float y00 = t0[0] + t0[1] + t0[2];
        float y01 = t0[1] - t0[2] - t0[3];
        float y10 = t1[0] + t1[1] + t1[2];
        float y11 = t1[1] - t1[2] - t1[3];
        Y[k][0] = y00; Y[k][1] = y01; Y[k][2] = y10; Y[k][3] = y11;
        s1 += (y00 + y01) + (y10 + y11);
        s2 += y00 * y00 + y01 * y01 + y10 * y10 + y11 * y11;
    }

#pragma unroll
    for (int o = 16; o > 0; o >>= 1) {
        s1 += __shfl_xor_sync(0xffffffffu, s1, o);
        s2 += __shfl_xor_sync(0xffffffffu, s2, o);
    }
    __shared__ float r1[8], r2[8];
    __shared__ float sh_mu, sh_rs;
    if ((t & 31) == 0) { r1[t >> 5] = s1; r2[t >> 5] = s2; }
    __syncthreads();
    if (t < 8) {
        s1 = r1[t]; s2 = r2[t];
#pragma unroll
        for (int o = 4; o > 0; o >>= 1) {
            s1 += __shfl_xor_sync(0xffu, s1, o);
            s2 += __shfl_xor_sync(0xffu, s2, o);
        }
        if (t == 0) {
            float mu = s1 * (1.f / 4096.f);
            float var = s2 * (1.f / 4096.f) - mu * mu;
            sh_mu = mu;
            sh_rs = rsqrtf(var + 1e-5f);
        }
    }
    __syncthreads();

    const float mu = sh_mu, rs = sh_rs;
    const float* cw = g_cwT + co * NCLS;
    const float* cb = g_cbT + co * NCLS;
    const int* lb = label + (size_t)b * HWN;
    float* ob = out + (size_t)bc * HWN;

#pragma unroll
    for (int k = 0; k < 4; k++) {
        int tpos = t + k * 256;
        int ty = tpos >> 5, tx = tpos & 31;
        int off = (2 * ty) * 64 + 2 * tx;
        int2 l0 = *(const int2*)(lb + off);
        int2 l1 = *(const int2*)(lb + off + 64);
        float2 o0, o1;
        o0.x = (Y[k][0] - mu) * rs * cw[l0.x] + cb[l0.x];
        o0.y = (Y[k][1] - mu) * rs * cw[l0.y] + cb[l0.y];
        o1.x = (Y[k][2] - mu) * rs * cw[l1.x] + cb[l1.x];
        o1.y = (Y[k][3] - mu) * rs * cw[l1.y] + cb[l1.y];
        *(float2*)(ob + off) = o0;
        *(float2*)(ob + off + 64) = o1;
    }
}

// ---------------- launch ----------------
extern "C" void kernel_launch(void* const* d_in, const int* in_sizes, int n_in,
                              void* d_out, int out_size)
{
    const float* input       = (const float*)d_in[0];
    const float* style       = (const float*)d_in[1];
    const float* class_style = (const float*)d_in[2];
    const float* weight      = (const float*)d_in[3];
    const float* mod_w       = (const float*)d_in[4];
    const float* mod_b       = (const float*)d_in[5];
    const float* cw_w        = (const float*)d_in[6];
    const float* cw_b        = (const float*)d_in[7];
    const float* cb_w        = (const float*)d_in[8];
    const float* cb_b        = (const float*)d_in[9];
    const int*   label       = (const int*)d_in[10];
    float* out = (float*)d_out;

    cudaFuncSetAttribute(wgemm_kernel,
                         cudaFuncAttributeMaxDynamicSharedMemorySize, WG_SMEM);

    int eql_blocks = (EQL_W0 + 2 * EQL_W1 + 7) / 8;
    eqlin_all_kernel<<<eql_blocks, 256>>>(style, class_style, mod_w, mod_b,
                                          cw_w, cw_b, cb_w, cb_b);

    uprep_kernel<<<(CO_N * CI_N + 255) / 256, 256>>>(weight);
    vprep_kernel<<<BB * 256, 256>>>(input);

    wgemm_kernel<<<8 * 32 * 4, 256, WG_SMEM>>>();

    fuse_kernel<<<BB * CO_N, 256>>>(label, out);
}